// round 15
// baseline (speedup 1.0000x reference)
#include <cuda_runtime.h>
#include <cuda_fp16.h>
#include <math.h>
#include <stdint.h>

// Problem constants
#define BATCH 512
#define HDIM  64
#define OBS   8
#define PRE   12
#define G3    192   // 3*H
#define NBUF  (PRE + 1)

// Scratch (device globals — no allocation allowed)
__device__ float   g_h[BATCH * HDIM];                // GRU hidden state (block-private)
// u per-step buffers, f16 pairs: [step][(j>>3)*256 + kp*8 + (j&7)] = half2{u[j][2kp], u[j][2kp+1]}
__device__ __half2 g_uh[NBUF][(BATCH / 8) * 32 * 8];
// hpart per-step buffers, f16 pairs: same layout over c
__device__ __half2 g_hph[NBUF][(BATCH / 8) * 32 * 8];
__device__ __align__(16) float g_WihT[HDIM * G3];    // W_ih transposed [d][g]
__device__ __align__(16) float g_WhhT[HDIM * G3];    // W_hh transposed [d][g]
// f16 B fragments for m16n8k16: [(ctp*4 + kt16)*32 + lane] = {b0_ct0, b1_ct0, b0_ct1, b1_ct1}
__device__ uint4   g_B4[16 * 32];
// grid barrier state
__device__ unsigned g_bar_cnt;
__device__ unsigned g_bar_rel;

__device__ __forceinline__ uint32_t h2u(__half2 h) {
    return *reinterpret_cast<uint32_t*>(&h);
}

// m16n8k16 f16 MMA, f32 accumulate
__device__ __forceinline__ void mma_f16(float* d,
                                        uint32_t a0, uint32_t a1, uint32_t a2, uint32_t a3,
                                        uint32_t b0, uint32_t b1) {
    asm volatile("mma.sync.aligned.m16n8k16.row.col.f32.f16.f16.f32 "
                 "{%0,%1,%2,%3}, {%4,%5,%6,%7}, {%8,%9}, {%0,%1,%2,%3};"
                 : "+f"(d[0]), "+f"(d[1]), "+f"(d[2]), "+f"(d[3])
                 : "r"(a0), "r"(a1), "r"(a2), "r"(a3), "r"(b0), "r"(b1));
}

__device__ __forceinline__ float fsigmoid(float x) {
    return 1.0f / (1.0f + __expf(-x));
}
__device__ __forceinline__ float ftanh(float x) {
    return 2.0f / (1.0f + __expf(-2.0f * x)) - 1.0f;
}

// index helper: half2 pair buffers (u and hp share the layout)
__device__ __forceinline__ int pair_idx(int j, int p) {   // p in [0,32)
    return (j >> 3) * 256 + p * 8 + (j & 7);
}

// ---------------------------------------------------------------------------
// Init: copy group_track into out, build u/hp (f16, buffer 0), zero GRU h and
// barrier state, transpose W_ih / W_hh, precompute f16 B fragments.
// Grid: BATCH + G3 + 16 blocks x 64 threads.
// ---------------------------------------------------------------------------
__global__ void init_kernel(const float* __restrict__ hidden,
                            const float* __restrict__ gt,
                            const float* __restrict__ W_ih,
                            const float* __restrict__ W_hh,
                            const float* __restrict__ W_rel,
                            const float* __restrict__ W_pool,
                            const float* __restrict__ b_pool,
                            float* __restrict__ out)
{
    __shared__ float tmp_s[HDIM];
    int bid = blockIdx.x;
    int c = threadIdx.x;
    if (bid == 0 && c == 0) { g_bar_cnt = 0u; g_bar_rel = 0u; }
    if (bid < BATCH) {
        int i = bid;
        // copy observed track: out[i, 0:8, :]
        if (c < 2 * OBS) out[i * 2 * (OBS + PRE) + c] = gt[i * 2 * OBS + c];
        float px = gt[i * 2 * OBS + 2 * (OBS - 1) + 0];
        float py = gt[i * 2 * OBS + 2 * (OBS - 1) + 1];
        if (c < 32) {
            float u0 = px * W_rel[2 * c]     + py * W_rel[HDIM + 2 * c];
            float u1 = px * W_rel[2 * c + 1] + py * W_rel[HDIM + 2 * c + 1];
            g_uh[0][pair_idx(i, c)] = __floats2half2_rn(u0, u1);
        }
        // hp (buffer 0) from hidden_state
        float acc = b_pool[c];
        #pragma unroll 8
        for (int d = 0; d < HDIM; ++d)
            acc += hidden[i * HDIM + d] * W_pool[(HDIM + d) * HDIM + c];
        tmp_s[c] = acc;
        g_h[i * HDIM + c] = 0.0f;
        __syncthreads();
        if (c < 32)
            g_hph[0][pair_idx(i, c)] = __floats2half2_rn(tmp_s[2 * c], tmp_s[2 * c + 1]);
    } else if (bid < BATCH + G3) {
        int g = bid - BATCH;   // 0..191
        int d = c;             // 0..63
        g_WihT[d * G3 + g] = W_ih[g * HDIM + d];
        g_WhhT[d * G3 + g] = W_hh[g * HDIM + d];
    } else if (c < 32) {
        // f16 B fragments for one (ctp, kt16)
        int q = bid - (BATCH + G3);   // 0..15
        int kt16 = q & 3, ctp = q >> 2;
        int tig = c & 3, gid = c >> 2;
        int k0 = kt16 * 16;
        int c0 = ctp * 16 + gid;      // ct0 column
        int c1 = c0 + 8;              // ct1 column
        uint32_t b00 = h2u(__floats2half2_rn(W_pool[(k0 + 2 * tig) * HDIM + c0],
                                             W_pool[(k0 + 2 * tig + 1) * HDIM + c0]));
        uint32_t b10 = h2u(__floats2half2_rn(W_pool[(k0 + 8 + 2 * tig) * HDIM + c0],
                                             W_pool[(k0 + 8 + 2 * tig + 1) * HDIM + c0]));
        uint32_t b01 = h2u(__floats2half2_rn(W_pool[(k0 + 2 * tig) * HDIM + c1],
                                             W_pool[(k0 + 2 * tig + 1) * HDIM + c1]));
        uint32_t b11 = h2u(__floats2half2_rn(W_pool[(k0 + 8 + 2 * tig) * HDIM + c1],
                                             W_pool[(k0 + 8 + 2 * tig + 1) * HDIM + c1]));
        g_B4[q * 32 + c] = make_uint4(b00, b10, b01, b11);
    }
}

// ---------------------------------------------------------------------------
// Persistent fused decoder, 8-warp blocks for 2x warp occupancy:
// 512 blocks x 256 threads, __launch_bounds__(256,4) -> 64 regs/thread ->
// 4 blocks/SM co-resident (spin barrier safe), 32 warps/SM (vs 16 before).
// Each warp handles 64 j as 4 tiles of ONE m16 jtile (small register state).
// Mainloop math identical to the 192.7us kernel; only the work split changed.
// ---------------------------------------------------------------------------
__global__ void __launch_bounds__(256, 4) decode_kernel(
    const float* __restrict__ b_rel,
    const float* __restrict__ W_emb, const float* __restrict__ b_emb,
    const float* __restrict__ b_ih,  const float* __restrict__ b_hh,
    const float* __restrict__ W_pos, const float* __restrict__ b_pos,
    const float* __restrict__ W_rel, const float* __restrict__ W_pool,
    const float* __restrict__ b_pool, float* __restrict__ out)
{
    __shared__ __half2 ar_s[32];      // pair {b_rel - u_i} at kp
    __shared__ float red_s[8][HDIM];  // cross-warp max reduction (8 warps)
    __shared__ float pooled_s[HDIM];
    __shared__ float pos_s[2];
    __shared__ float emb_s[HDIM];
    __shared__ float hv_s[HDIM];
    __shared__ float hn_s[HDIM];
    __shared__ __align__(16) float gate_s[6][HDIM];
    __shared__ float4 hpr_s[16][4];

    int i = blockIdx.x;
    int t = threadIdx.x;
    int w = t >> 5, l = t & 31;
    int gid = l >> 2, tig = l & 3;

    #pragma unroll 1
    for (int step = 0; step < PRE; ++step) {
        const __half2* __restrict__ uhr = g_uh[step];
        const __half2* __restrict__ hph = g_hph[step];

        if (t < 32) {
            float2 ui = __half22float2(uhr[pair_idx(i, t)]);
            ar_s[t] = __floats2half2_rn(b_rel[2 * t] - ui.x, b_rel[2 * t + 1] - ui.y);
        }
        __syncthreads();

        float mx[8][2];
        #pragma unroll
        for (int ct = 0; ct < 8; ++ct) { mx[ct][0] = 0.0f; mx[ct][1] = 0.0f; }  // relu => max>=0

        // warp w handles tiles tl = p*8 + w (16 j each): 4 x 16 = 64 j
        for (int p = 0; p < 4; ++p) {
            int tl = p * 8 + w;
            int rb = tl * 512;          // half2 base for rows tl*16 .. +7; +256 for +8..+15

            // A fragments: e = hmax2(hadd2(u_j, ar), 0), packed f16, 1 jtile x 4 kt16
            __half2 zero2 = __float2half2_rn(0.0f);
            uint32_t afr[4][4];
            #pragma unroll
            for (int kt = 0; kt < 4; ++kt) {
                int kp0 = kt * 8 + tig;     // cols 2kp0, 2kp0+1
                int kp1 = kp0 + 4;          // cols +8
                __half2 ar0 = ar_s[kp0], ar1 = ar_s[kp1];
                __half2 v00 = uhr[rb + kp0 * 8 + gid];          // row gid
                __half2 v10 = uhr[rb + 256 + kp0 * 8 + gid];    // row gid+8
                __half2 v01 = uhr[rb + kp1 * 8 + gid];
                __half2 v11 = uhr[rb + 256 + kp1 * 8 + gid];
                afr[kt][0] = h2u(__hmax2(__hadd2(v00, ar0), zero2));
                afr[kt][1] = h2u(__hmax2(__hadd2(v10, ar0), zero2));
                afr[kt][2] = h2u(__hmax2(__hadd2(v01, ar1), zero2));
                afr[kt][3] = h2u(__hmax2(__hadd2(v11, ar1), zero2));
            }

            // ct pairs: 2 independent accumulator chains, 4 k16-steps each
            #pragma unroll
            for (int ctp = 0; ctp < 4; ++ctp) {
                int ct0 = 2 * ctp, ct1 = 2 * ctp + 1;
                // C init = hpart fragments (f16 -> f32): 4 LDG.32
                float2 h00 = __half22float2(hph[rb + (ct0 * 4 + tig) * 8 + gid]);
                float2 h01 = __half22float2(hph[rb + 256 + (ct0 * 4 + tig) * 8 + gid]);
                float2 h10 = __half22float2(hph[rb + (ct1 * 4 + tig) * 8 + gid]);
                float2 h11 = __half22float2(hph[rb + 256 + (ct1 * 4 + tig) * 8 + gid]);
                float d0[4] = {h00.x, h00.y, h01.x, h01.y};   // ct0
                float d1[4] = {h10.x, h10.y, h11.x, h11.y};   // ct1

                #pragma unroll
                for (int kt = 0; kt < 4; ++kt) {
                    uint4 B = g_B4[(ctp * 4 + kt) * 32 + l];
                    mma_f16(d0, afr[kt][0], afr[kt][1], afr[kt][2], afr[kt][3], B.x, B.y);
                    mma_f16(d1, afr[kt][0], afr[kt][1], afr[kt][2], afr[kt][3], B.z, B.w);
                }
                mx[ct0][0] = fmaxf(mx[ct0][0], fmaxf(d0[0], d0[2]));
                mx[ct0][1] = fmaxf(mx[ct0][1], fmaxf(d0[1], d0[3]));
                mx[ct1][0] = fmaxf(mx[ct1][0], fmaxf(d1[0], d1[2]));
                mx[ct1][1] = fmaxf(mx[ct1][1], fmaxf(d1[1], d1[3]));
            }
        }

        // Reduce across lane groups (gid), write per-warp result
        #pragma unroll
        for (int ct = 0; ct < 8; ++ct) {
            #pragma unroll
            for (int pp = 0; pp < 2; ++pp) {
                float v = mx[ct][pp];
                v = fmaxf(v, __shfl_xor_sync(0xffffffffu, v, 4));
                v = fmaxf(v, __shfl_xor_sync(0xffffffffu, v, 8));
                v = fmaxf(v, __shfl_xor_sync(0xffffffffu, v, 16));
                if (gid == 0) red_s[w][ct * 8 + 2 * tig + pp] = v;
            }
        }
        __syncthreads();
        if (t < HDIM) {
            float m0 = fmaxf(fmaxf(red_s[0][t], red_s[1][t]), fmaxf(red_s[2][t], red_s[3][t]));
            float m1 = fmaxf(fmaxf(red_s[4][t], red_s[5][t]), fmaxf(red_s[6][t], red_s[7][t]));
            pooled_s[t] = fmaxf(m0, m1);
        }
        __syncthreads();

        // ---- update tail ----
        if (w == 0) {
            float p0 = pooled_s[l], p1 = pooled_s[l + 32];
            float px = p0 * W_pos[l * 2 + 0] + p1 * W_pos[(l + 32) * 2 + 0];
            float py = p0 * W_pos[l * 2 + 1] + p1 * W_pos[(l + 32) * 2 + 1];
            #pragma unroll
            for (int s = 16; s; s >>= 1) {
                px += __shfl_xor_sync(0xffffffffu, px, s);
                py += __shfl_xor_sync(0xffffffffu, py, s);
            }
            if (l == 0) {
                px += b_pos[0]; py += b_pos[1];
                out[i * 2 * (OBS + PRE) + (OBS + step) * 2 + 0] = px;
                out[i * 2 * (OBS + PRE) + (OBS + step) * 2 + 1] = py;
                pos_s[0] = px; pos_s[1] = py;
            }
        }
        __syncthreads();

        float px = pos_s[0], py = pos_s[1];
        if (t < 32) {
            // next-step u pair (f16, fresh buffer: step+1)
            float u0 = px * W_rel[2 * t]     + py * W_rel[HDIM + 2 * t];
            float u1 = px * W_rel[2 * t + 1] + py * W_rel[HDIM + 2 * t + 1];
            g_uh[step + 1][pair_idx(i, t)] = __floats2half2_rn(u0, u1);
        }
        if (t < HDIM) {
            emb_s[t] = px * W_emb[t] + py * W_emb[HDIM + t] + b_emb[t];
            hv_s[t]  = g_h[i * HDIM + t];
        }
        __syncthreads();

        // Phase A: 6 GRU gate matvecs via float4 (thread = (gate g, c-quad q))
        if (t < 96) {
            int g = t >> 4, q = t & 15;
            int gg = (g < 3) ? g : g - 3;
            const float* Wt   = (g < 3) ? g_WihT : g_WhhT;
            const float* bias = (g < 3) ? b_ih : b_hh;
            const float* src  = (g < 3) ? emb_s : hv_s;
            float4 acc = *(const float4*)&bias[gg * 64 + q * 4];
            #pragma unroll 8
            for (int d = 0; d < HDIM; ++d) {
                float4 wv = *(const float4*)&Wt[d * G3 + gg * 64 + q * 4];
                float s = src[d];
                acc.x += s * wv.x; acc.y += s * wv.y;
                acc.z += s * wv.z; acc.w += s * wv.w;
            }
            *(float4*)&gate_s[g][q * 4] = acc;
        }
        __syncthreads();
        if (t < HDIM) {
            int c = t;
            float r = fsigmoid(gate_s[0][c] + gate_s[3][c]);
            float z = fsigmoid(gate_s[1][c] + gate_s[4][c]);
            float n = ftanh(gate_s[2][c] + r * gate_s[5][c]);
            float hn = (1.0f - z) * n + z * hv_s[c];
            g_h[i * HDIM + c] = hn;
            hn_s[c] = hn;
        }
        __syncthreads();

        // Phase B: hp = hn @ Wp2 + b_pool, float4 partials then reduce, f16 store
        if (t < 64) {
            int q = t & 15, dh = t >> 4;
            float4 acc = make_float4(0.0f, 0.0f, 0.0f, 0.0f);
            #pragma unroll
            for (int dd = 0; dd < 16; ++dd) {
                int d = dh * 16 + dd;
                float4 wv = *(const float4*)&W_pool[(HDIM + d) * HDIM + q * 4];
                float s = hn_s[d];
                acc.x += s * wv.x; acc.y += s * wv.y;
                acc.z += s * wv.z; acc.w += s * wv.w;
            }
            hpr_s[q][dh] = acc;
        }
        __syncthreads();
        if (t < 16) {
            int q = t;
            float4 a0 = hpr_s[q][0], a1 = hpr_s[q][1], a2 = hpr_s[q][2], a3 = hpr_s[q][3];
            float c0 = a0.x + a1.x + a2.x + a3.x + b_pool[q * 4 + 0];
            float c1 = a0.y + a1.y + a2.y + a3.y + b_pool[q * 4 + 1];
            float c2 = a0.z + a1.z + a2.z + a3.z + b_pool[q * 4 + 2];
            float c3 = a0.w + a1.w + a2.w + a3.w + b_pool[q * 4 + 3];
            g_hph[step + 1][pair_idx(i, 2 * q)]     = __floats2half2_rn(c0, c1);
            g_hph[step + 1][pair_idx(i, 2 * q + 1)] = __floats2half2_rn(c2, c3);
        }

        // ---- grid barrier (skip after last step) ----
        if (step == PRE - 1) break;
        __syncthreads();
        if (t == 0) {
            __threadfence();   // release: u/hp stores visible GPU-wide
            unsigned target = (unsigned)BATCH * (unsigned)(step + 1);
            unsigned old = atomicAdd(&g_bar_cnt, 1u);
            if (old + 1u == target) {
                atomicExch(&g_bar_rel, (unsigned)(step + 1));
            } else {
                unsigned v;
                do {
                    asm volatile("ld.global.cg.u32 %0, [%1];" : "=r"(v) : "l"(&g_bar_rel));
                    if (v >= (unsigned)(step + 1)) break;
                    __nanosleep(64);
                } while (true);
            }
            __threadfence();
        }
        __syncthreads();
    }
}

// ---------------------------------------------------------------------------
extern "C" void kernel_launch(void* const* d_in, const int* in_sizes, int n_in,
                              void* d_out, int out_size)
{
    const float* hidden = (const float*)d_in[0];
    const float* gt     = (const float*)d_in[1];
    const float* W_emb  = (const float*)d_in[2];
    const float* b_emb  = (const float*)d_in[3];
    const float* W_ih   = (const float*)d_in[4];
    const float* W_hh   = (const float*)d_in[5];
    const float* b_ih   = (const float*)d_in[6];
    const float* b_hh   = (const float*)d_in[7];
    const float* W_pos  = (const float*)d_in[8];
    const float* b_pos  = (const float*)d_in[9];
    const float* W_rel  = (const float*)d_in[10];
    const float* b_rel  = (const float*)d_in[11];
    const float* W_pool = (const float*)d_in[12];
    const float* b_pool = (const float*)d_in[13];
    float* out = (float*)d_out;

    init_kernel<<<BATCH + G3 + 16, 64>>>(hidden, gt, W_ih, W_hh, W_rel, W_pool, b_pool, out);
    decode_kernel<<<BATCH, 256>>>(b_rel, W_emb, b_emb, b_ih, b_hh,
                                  W_pos, b_pos, W_rel, W_pool, b_pool, out);
}

// round 16
// speedup vs baseline: 1.6738x; 1.6738x over previous
#include <cuda_runtime.h>
#include <cuda_fp16.h>
#include <math.h>
#include <stdint.h>

// Problem constants
#define BATCH 512
#define HDIM  64
#define OBS   8
#define PRE   12
#define G3    192   // 3*H
#define NBUF  (PRE + 1)

// Scratch (device globals — no allocation allowed)
__device__ float   g_h[BATCH * HDIM];                // GRU hidden state (block-private)
// u per-step buffers, f16 pairs: [step][(j>>3)*256 + kp*8 + (j&7)] = half2{u[j][2kp], u[j][2kp+1]}
__device__ __half2 g_uh[NBUF][(BATCH / 8) * 32 * 8];
// hpart per-step buffers, f16 pairs: same layout over c
__device__ __half2 g_hph[NBUF][(BATCH / 8) * 32 * 8];
__device__ __align__(16) float g_WihT[HDIM * G3];    // W_ih transposed [d][g]
__device__ __align__(16) float g_WhhT[HDIM * G3];    // W_hh transposed [d][g]
// f16 B fragments for m16n8k16: [(ctp*4 + kt16)*32 + lane] = {b0_ct0, b1_ct0, b0_ct1, b1_ct1}
__device__ uint4   g_B4[16 * 32];
// grid barrier state
__device__ unsigned g_bar_cnt;
__device__ unsigned g_bar_rel;

__device__ __forceinline__ uint32_t h2u(__half2 h) {
    return *reinterpret_cast<uint32_t*>(&h);
}

// m16n8k16 f16 MMA, f32 accumulate
__device__ __forceinline__ void mma_f16(float* d,
                                        uint32_t a0, uint32_t a1, uint32_t a2, uint32_t a3,
                                        uint32_t b0, uint32_t b1) {
    asm volatile("mma.sync.aligned.m16n8k16.row.col.f32.f16.f16.f32 "
                 "{%0,%1,%2,%3}, {%4,%5,%6,%7}, {%8,%9}, {%0,%1,%2,%3};"
                 : "+f"(d[0]), "+f"(d[1]), "+f"(d[2]), "+f"(d[3])
                 : "r"(a0), "r"(a1), "r"(a2), "r"(a3), "r"(b0), "r"(b1));
}

__device__ __forceinline__ float fsigmoid(float x) {
    return 1.0f / (1.0f + __expf(-x));
}
__device__ __forceinline__ float ftanh(float x) {
    return 2.0f / (1.0f + __expf(-2.0f * x)) - 1.0f;
}

// index helper: half2 pair buffers (u and hp share the layout)
__device__ __forceinline__ int pair_idx(int j, int p) {   // p in [0,32)
    return (j >> 3) * 256 + p * 8 + (j & 7);
}

// ---------------------------------------------------------------------------
// Init: copy group_track into out, build u/hp (f16, buffer 0), zero GRU h and
// barrier state, transpose W_ih / W_hh, precompute f16 B fragments.
// Grid: BATCH + G3 + 16 blocks x 64 threads.
// ---------------------------------------------------------------------------
__global__ void init_kernel(const float* __restrict__ hidden,
                            const float* __restrict__ gt,
                            const float* __restrict__ W_ih,
                            const float* __restrict__ W_hh,
                            const float* __restrict__ W_rel,
                            const float* __restrict__ W_pool,
                            const float* __restrict__ b_pool,
                            float* __restrict__ out)
{
    __shared__ float tmp_s[HDIM];
    int bid = blockIdx.x;
    int c = threadIdx.x;
    if (bid == 0 && c == 0) { g_bar_cnt = 0u; g_bar_rel = 0u; }
    if (bid < BATCH) {
        int i = bid;
        // copy observed track: out[i, 0:8, :]
        if (c < 2 * OBS) out[i * 2 * (OBS + PRE) + c] = gt[i * 2 * OBS + c];
        float px = gt[i * 2 * OBS + 2 * (OBS - 1) + 0];
        float py = gt[i * 2 * OBS + 2 * (OBS - 1) + 1];
        if (c < 32) {
            float u0 = px * W_rel[2 * c]     + py * W_rel[HDIM + 2 * c];
            float u1 = px * W_rel[2 * c + 1] + py * W_rel[HDIM + 2 * c + 1];
            g_uh[0][pair_idx(i, c)] = __floats2half2_rn(u0, u1);
        }
        // hp (buffer 0) from hidden_state
        float acc = b_pool[c];
        #pragma unroll 8
        for (int d = 0; d < HDIM; ++d)
            acc += hidden[i * HDIM + d] * W_pool[(HDIM + d) * HDIM + c];
        tmp_s[c] = acc;
        g_h[i * HDIM + c] = 0.0f;
        __syncthreads();
        if (c < 32)
            g_hph[0][pair_idx(i, c)] = __floats2half2_rn(tmp_s[2 * c], tmp_s[2 * c + 1]);
    } else if (bid < BATCH + G3) {
        int g = bid - BATCH;   // 0..191
        int d = c;             // 0..63
        g_WihT[d * G3 + g] = W_ih[g * HDIM + d];
        g_WhhT[d * G3 + g] = W_hh[g * HDIM + d];
    } else if (c < 32) {
        // f16 B fragments for one (ctp, kt16)
        int q = bid - (BATCH + G3);   // 0..15
        int kt16 = q & 3, ctp = q >> 2;
        int tig = c & 3, gid = c >> 2;
        int k0 = kt16 * 16;
        int c0 = ctp * 16 + gid;      // ct0 column
        int c1 = c0 + 8;              // ct1 column
        uint32_t b00 = h2u(__floats2half2_rn(W_pool[(k0 + 2 * tig) * HDIM + c0],
                                             W_pool[(k0 + 2 * tig + 1) * HDIM + c0]));
        uint32_t b10 = h2u(__floats2half2_rn(W_pool[(k0 + 8 + 2 * tig) * HDIM + c0],
                                             W_pool[(k0 + 8 + 2 * tig + 1) * HDIM + c0]));
        uint32_t b01 = h2u(__floats2half2_rn(W_pool[(k0 + 2 * tig) * HDIM + c1],
                                             W_pool[(k0 + 2 * tig + 1) * HDIM + c1]));
        uint32_t b11 = h2u(__floats2half2_rn(W_pool[(k0 + 8 + 2 * tig) * HDIM + c1],
                                             W_pool[(k0 + 8 + 2 * tig + 1) * HDIM + c1]));
        g_B4[q * 32 + c] = make_uint4(b00, b10, b01, b11);
    }
}

// ---------------------------------------------------------------------------
// Persistent fused decoder — R11 math with a slimmer per-warp loop:
// 512 blocks x 128 threads, __launch_bounds__(128, 5) -> <=102 regs/thread
// (natural usage of the 1-jtile loop ~90 -> no spills), 5 blocks/SM -> 20
// warps/SM (vs 16 at 128 regs). Warp w handles 8 jtiles of 16 rows
// (tl = p*4 + w). Per (jtile, ct) accumulator the arithmetic and order are
// bit-identical to the 192.7us kernel.
// ---------------------------------------------------------------------------
__global__ void __launch_bounds__(128, 5) decode_kernel(
    const float* __restrict__ b_rel,
    const float* __restrict__ W_emb, const float* __restrict__ b_emb,
    const float* __restrict__ b_ih,  const float* __restrict__ b_hh,
    const float* __restrict__ W_pos, const float* __restrict__ b_pos,
    const float* __restrict__ W_rel, const float* __restrict__ W_pool,
    const float* __restrict__ b_pool, float* __restrict__ out)
{
    __shared__ __half2 ar_s[32];      // pair {b_rel - u_i} at kp
    __shared__ float red_s[4][HDIM];  // cross-warp max reduction
    __shared__ float pooled_s[HDIM];
    __shared__ float pos_s[2];
    __shared__ float emb_s[HDIM];
    __shared__ float hv_s[HDIM];
    __shared__ float hn_s[HDIM];
    __shared__ __align__(16) float gate_s[6][HDIM];
    __shared__ float4 hpr_s[16][4];

    int i = blockIdx.x;
    int t = threadIdx.x;
    int w = t >> 5, l = t & 31;
    int gid = l >> 2, tig = l & 3;

    #pragma unroll 1
    for (int step = 0; step < PRE; ++step) {
        const __half2* __restrict__ uhr = g_uh[step];
        const __half2* __restrict__ hph = g_hph[step];

        if (t < 32) {
            float2 ui = __half22float2(uhr[pair_idx(i, t)]);
            ar_s[t] = __floats2half2_rn(b_rel[2 * t] - ui.x, b_rel[2 * t + 1] - ui.y);
        }
        __syncthreads();

        float mx[8][2];
        #pragma unroll
        for (int ct = 0; ct < 8; ++ct) { mx[ct][0] = 0.0f; mx[ct][1] = 0.0f; }  // relu => max>=0

        // warp w handles jtiles tl = p*4 + w (16 j each): 8 x 16 = 128 j
        #pragma unroll 1
        for (int p = 0; p < 8; ++p) {
            int tl = p * 4 + w;
            int rb = tl * 512;          // half2 base: rows tl*16..+7; +256 for +8..+15

            // A fragments: e = hmax2(hadd2(u_j, ar), 0), packed f16, 1 jtile x 4 kt16
            __half2 zero2 = __float2half2_rn(0.0f);
            uint32_t afr[4][4];
            #pragma unroll
            for (int kt = 0; kt < 4; ++kt) {
                int kp0 = kt * 8 + tig;     // cols 2kp0, 2kp0+1
                int kp1 = kp0 + 4;          // cols +8
                __half2 ar0 = ar_s[kp0], ar1 = ar_s[kp1];
                __half2 v00 = uhr[rb + kp0 * 8 + gid];          // row gid
                __half2 v10 = uhr[rb + 256 + kp0 * 8 + gid];    // row gid+8
                __half2 v01 = uhr[rb + kp1 * 8 + gid];
                __half2 v11 = uhr[rb + 256 + kp1 * 8 + gid];
                afr[kt][0] = h2u(__hmax2(__hadd2(v00, ar0), zero2));
                afr[kt][1] = h2u(__hmax2(__hadd2(v10, ar0), zero2));
                afr[kt][2] = h2u(__hmax2(__hadd2(v01, ar1), zero2));
                afr[kt][3] = h2u(__hmax2(__hadd2(v11, ar1), zero2));
            }

            // ct pairs: 2 independent accumulator chains, 4 k16-steps each
            #pragma unroll
            for (int ctp = 0; ctp < 4; ++ctp) {
                int ct0 = 2 * ctp, ct1 = 2 * ctp + 1;
                // C init = hpart fragments (f16 -> f32): 4 LDG.32
                float2 h00 = __half22float2(hph[rb + (ct0 * 4 + tig) * 8 + gid]);
                float2 h01 = __half22float2(hph[rb + 256 + (ct0 * 4 + tig) * 8 + gid]);
                float2 h10 = __half22float2(hph[rb + (ct1 * 4 + tig) * 8 + gid]);
                float2 h11 = __half22float2(hph[rb + 256 + (ct1 * 4 + tig) * 8 + gid]);
                float d0[4] = {h00.x, h00.y, h01.x, h01.y};   // ct0
                float d1[4] = {h10.x, h10.y, h11.x, h11.y};   // ct1

                #pragma unroll
                for (int kt = 0; kt < 4; ++kt) {
                    uint4 B = g_B4[(ctp * 4 + kt) * 32 + l];
                    mma_f16(d0, afr[kt][0], afr[kt][1], afr[kt][2], afr[kt][3], B.x, B.y);
                    mma_f16(d1, afr[kt][0], afr[kt][1], afr[kt][2], afr[kt][3], B.z, B.w);
                }
                mx[ct0][0] = fmaxf(mx[ct0][0], fmaxf(d0[0], d0[2]));
                mx[ct0][1] = fmaxf(mx[ct0][1], fmaxf(d0[1], d0[3]));
                mx[ct1][0] = fmaxf(mx[ct1][0], fmaxf(d1[0], d1[2]));
                mx[ct1][1] = fmaxf(mx[ct1][1], fmaxf(d1[1], d1[3]));
            }
        }

        // Reduce across lane groups (gid), write per-warp result
        #pragma unroll
        for (int ct = 0; ct < 8; ++ct) {
            #pragma unroll
            for (int pp = 0; pp < 2; ++pp) {
                float v = mx[ct][pp];
                v = fmaxf(v, __shfl_xor_sync(0xffffffffu, v, 4));
                v = fmaxf(v, __shfl_xor_sync(0xffffffffu, v, 8));
                v = fmaxf(v, __shfl_xor_sync(0xffffffffu, v, 16));
                if (gid == 0) red_s[w][ct * 8 + 2 * tig + pp] = v;
            }
        }
        __syncthreads();
        if (t < HDIM)
            pooled_s[t] = fmaxf(fmaxf(red_s[0][t], red_s[1][t]), fmaxf(red_s[2][t], red_s[3][t]));
        __syncthreads();

        // ---- update tail ----
        if (w == 0) {
            float p0 = pooled_s[l], p1 = pooled_s[l + 32];
            float px = p0 * W_pos[l * 2 + 0] + p1 * W_pos[(l + 32) * 2 + 0];
            float py = p0 * W_pos[l * 2 + 1] + p1 * W_pos[(l + 32) * 2 + 1];
            #pragma unroll
            for (int s = 16; s; s >>= 1) {
                px += __shfl_xor_sync(0xffffffffu, px, s);
                py += __shfl_xor_sync(0xffffffffu, py, s);
            }
            if (l == 0) {
                px += b_pos[0]; py += b_pos[1];
                out[i * 2 * (OBS + PRE) + (OBS + step) * 2 + 0] = px;
                out[i * 2 * (OBS + PRE) + (OBS + step) * 2 + 1] = py;
                pos_s[0] = px; pos_s[1] = py;
            }
        }
        __syncthreads();

        float px = pos_s[0], py = pos_s[1];
        if (t < 32) {
            // next-step u pair (f16, fresh buffer: step+1)
            float u0 = px * W_rel[2 * t]     + py * W_rel[HDIM + 2 * t];
            float u1 = px * W_rel[2 * t + 1] + py * W_rel[HDIM + 2 * t + 1];
            g_uh[step + 1][pair_idx(i, t)] = __floats2half2_rn(u0, u1);
        }
        if (t < HDIM) {
            emb_s[t] = px * W_emb[t] + py * W_emb[HDIM + t] + b_emb[t];
            hv_s[t]  = g_h[i * HDIM + t];
        }
        __syncthreads();

        // Phase A: 6 GRU gate matvecs via float4 (thread = (gate g, c-quad q))
        if (t < 96) {
            int g = t >> 4, q = t & 15;
            int gg = (g < 3) ? g : g - 3;
            const float* Wt   = (g < 3) ? g_WihT : g_WhhT;
            const float* bias = (g < 3) ? b_ih : b_hh;
            const float* src  = (g < 3) ? emb_s : hv_s;
            float4 acc = *(const float4*)&bias[gg * 64 + q * 4];
            #pragma unroll 8
            for (int d = 0; d < HDIM; ++d) {
                float4 wv = *(const float4*)&Wt[d * G3 + gg * 64 + q * 4];
                float s = src[d];
                acc.x += s * wv.x; acc.y += s * wv.y;
                acc.z += s * wv.z; acc.w += s * wv.w;
            }
            *(float4*)&gate_s[g][q * 4] = acc;
        }
        __syncthreads();
        if (t < HDIM) {
            int c = t;
            float r = fsigmoid(gate_s[0][c] + gate_s[3][c]);
            float z = fsigmoid(gate_s[1][c] + gate_s[4][c]);
            float n = ftanh(gate_s[2][c] + r * gate_s[5][c]);
            float hn = (1.0f - z) * n + z * hv_s[c];
            g_h[i * HDIM + c] = hn;
            hn_s[c] = hn;
        }
        __syncthreads();

        // Phase B: hp = hn @ Wp2 + b_pool, float4 partials then reduce, f16 store
        if (t < 64) {
            int q = t & 15, dh = t >> 4;
            float4 acc = make_float4(0.0f, 0.0f, 0.0f, 0.0f);
            #pragma unroll
            for (int dd = 0; dd < 16; ++dd) {
                int d = dh * 16 + dd;
                float4 wv = *(const float4*)&W_pool[(HDIM + d) * HDIM + q * 4];
                float s = hn_s[d];
                acc.x += s * wv.x; acc.y += s * wv.y;
                acc.z += s * wv.z; acc.w += s * wv.w;
            }
            hpr_s[q][dh] = acc;
        }
        __syncthreads();
        if (t < 16) {
            int q = t;
            float4 a0 = hpr_s[q][0], a1 = hpr_s[q][1], a2 = hpr_s[q][2], a3 = hpr_s[q][3];
            float c0 = a0.x + a1.x + a2.x + a3.x + b_pool[q * 4 + 0];
            float c1 = a0.y + a1.y + a2.y + a3.y + b_pool[q * 4 + 1];
            float c2 = a0.z + a1.z + a2.z + a3.z + b_pool[q * 4 + 2];
            float c3 = a0.w + a1.w + a2.w + a3.w + b_pool[q * 4 + 3];
            g_hph[step + 1][pair_idx(i, 2 * q)]     = __floats2half2_rn(c0, c1);
            g_hph[step + 1][pair_idx(i, 2 * q + 1)] = __floats2half2_rn(c2, c3);
        }

        // ---- grid barrier (skip after last step) ----
        if (step == PRE - 1) break;
        __syncthreads();
        if (t == 0) {
            __threadfence();   // release: u/hp stores visible GPU-wide
            unsigned target = (unsigned)BATCH * (unsigned)(step + 1);
            unsigned old = atomicAdd(&g_bar_cnt, 1u);
            if (old + 1u == target) {
                atomicExch(&g_bar_rel, (unsigned)(step + 1));
            } else {
                unsigned v;
                do {
                    asm volatile("ld.global.cg.u32 %0, [%1];" : "=r"(v) : "l"(&g_bar_rel));
                    if (v >= (unsigned)(step + 1)) break;
                    __nanosleep(64);
                } while (true);
            }
            __threadfence();
        }
        __syncthreads();
    }
}

// ---------------------------------------------------------------------------
extern "C" void kernel_launch(void* const* d_in, const int* in_sizes, int n_in,
                              void* d_out, int out_size)
{
    const float* hidden = (const float*)d_in[0];
    const float* gt     = (const float*)d_in[1];
    const float* W_emb  = (const float*)d_in[2];
    const float* b_emb  = (const float*)d_in[3];
    const float* W_ih   = (const float*)d_in[4];
    const float* W_hh   = (const float*)d_in[5];
    const float* b_ih   = (const float*)d_in[6];
    const float* b_hh   = (const float*)d_in[7];
    const float* W_pos  = (const float*)d_in[8];
    const float* b_pos  = (const float*)d_in[9];
    const float* W_rel  = (const float*)d_in[10];
    const float* b_rel  = (const float*)d_in[11];
    const float* W_pool = (const float*)d_in[12];
    const float* b_pool = (const float*)d_in[13];
    float* out = (float*)d_out;

    init_kernel<<<BATCH + G3 + 16, 64>>>(hidden, gt, W_ih, W_hh, W_rel, W_pool, b_pool, out);
    decode_kernel<<<BATCH, 128>>>(b_rel, W_emb, b_emb, b_ih, b_hh,
                                  W_pos, b_pos, W_rel, W_pool, b_pool, out);
}

// round 17
// speedup vs baseline: 2.2106x; 1.3207x over previous
#include <cuda_runtime.h>
#include <cuda_fp16.h>
#include <math.h>
#include <stdint.h>

// Problem constants
#define BATCH 512
#define HDIM  64
#define OBS   8
#define PRE   12
#define G3    192   // 3*H
#define NBUF  (PRE + 1)

// Scratch (device globals — no allocation allowed)
__device__ float   g_h[BATCH * HDIM];                // GRU hidden state (block-private)
// u per-step buffers, f16 pairs: [step][(j>>3)*256 + kp*8 + (j&7)] = half2{u[j][2kp], u[j][2kp+1]}
__device__ __half2 g_uh[NBUF][(BATCH / 8) * 32 * 8];
// hpart per-step buffers, uint2 keyed by idx=(ctp*4+tig) in [0,16):
//   [step][(j>>3)*128 + idx*8 + (j&7)] =
//     { h2(hp[16ctp+2tig], hp[16ctp+2tig+1]), h2(hp[16ctp+8+2tig], hp[16ctp+8+2tig+1]) }
__device__ uint2   g_hpq[NBUF][(BATCH / 8) * 16 * 8];
__device__ __align__(16) float g_WihT[HDIM * G3];    // W_ih transposed [d][g]
__device__ __align__(16) float g_WhhT[HDIM * G3];    // W_hh transposed [d][g]
// f16 B fragments for m16n8k16: [(ctp*4 + kt16)*32 + lane] = {b0_ct0, b1_ct0, b0_ct1, b1_ct1}
__device__ uint4   g_B4[16 * 32];
// grid barrier state
__device__ unsigned g_bar_cnt;
__device__ unsigned g_bar_rel;

__device__ __forceinline__ uint32_t h2u(__half2 h) {
    return *reinterpret_cast<uint32_t*>(&h);
}
__device__ __forceinline__ __half2 u2h(uint32_t v) {
    return *reinterpret_cast<__half2*>(&v);
}
// pack two fp32 into f16x2: lo <- lo_f, hi <- hi_f (one instruction)
__device__ __forceinline__ __half2 packh2(float hi_f, float lo_f) {
    uint32_t r;
    asm("cvt.rn.f16x2.f32 %0, %1, %2;" : "=r"(r) : "f"(hi_f), "f"(lo_f));
    return u2h(r);
}

// m16n8k16 f16 MMA, f32 accumulate
__device__ __forceinline__ void mma_f16(float* d,
                                        uint32_t a0, uint32_t a1, uint32_t a2, uint32_t a3,
                                        uint32_t b0, uint32_t b1) {
    asm volatile("mma.sync.aligned.m16n8k16.row.col.f32.f16.f16.f32 "
                 "{%0,%1,%2,%3}, {%4,%5,%6,%7}, {%8,%9}, {%0,%1,%2,%3};"
                 : "+f"(d[0]), "+f"(d[1]), "+f"(d[2]), "+f"(d[3])
                 : "r"(a0), "r"(a1), "r"(a2), "r"(a3), "r"(b0), "r"(b1));
}

__device__ __forceinline__ float fsigmoid(float x) {
    return 1.0f / (1.0f + __expf(-x));
}
__device__ __forceinline__ float ftanh(float x) {
    return 2.0f / (1.0f + __expf(-2.0f * x)) - 1.0f;
}

// index helpers
__device__ __forceinline__ int pair_idx(int j, int p) {   // u buffer, p in [0,32)
    return (j >> 3) * 256 + p * 8 + (j & 7);
}
__device__ __forceinline__ int hpq_idx(int j, int idx) {  // hp buffer, idx in [0,16)
    return (j >> 3) * 128 + idx * 8 + (j & 7);
}

// ---------------------------------------------------------------------------
// Init: copy group_track into out, build u/hp (f16, buffer 0), zero GRU h and
// barrier state, transpose W_ih / W_hh, precompute f16 B fragments.
// Grid: BATCH + G3 + 16 blocks x 64 threads.
// ---------------------------------------------------------------------------
__global__ void init_kernel(const float* __restrict__ hidden,
                            const float* __restrict__ gt,
                            const float* __restrict__ W_ih,
                            const float* __restrict__ W_hh,
                            const float* __restrict__ W_rel,
                            const float* __restrict__ W_pool,
                            const float* __restrict__ b_pool,
                            float* __restrict__ out)
{
    __shared__ float tmp_s[HDIM];
    int bid = blockIdx.x;
    int c = threadIdx.x;
    if (bid == 0 && c == 0) { g_bar_cnt = 0u; g_bar_rel = 0u; }
    if (bid < BATCH) {
        int i = bid;
        // copy observed track: out[i, 0:8, :]
        if (c < 2 * OBS) out[i * 2 * (OBS + PRE) + c] = gt[i * 2 * OBS + c];
        float px = gt[i * 2 * OBS + 2 * (OBS - 1) + 0];
        float py = gt[i * 2 * OBS + 2 * (OBS - 1) + 1];
        if (c < 32) {
            float u0 = px * W_rel[2 * c]     + py * W_rel[HDIM + 2 * c];
            float u1 = px * W_rel[2 * c + 1] + py * W_rel[HDIM + 2 * c + 1];
            g_uh[0][pair_idx(i, c)] = __floats2half2_rn(u0, u1);
        }
        // hp (buffer 0) from hidden_state
        float acc = b_pool[c];
        #pragma unroll 8
        for (int d = 0; d < HDIM; ++d)
            acc += hidden[i * HDIM + d] * W_pool[(HDIM + d) * HDIM + c];
        tmp_s[c] = acc;
        g_h[i * HDIM + c] = 0.0f;
        __syncthreads();
        if (c < 16) {
            int ctp = c >> 2, tig = c & 3;
            int c0 = 16 * ctp + 2 * tig;
            g_hpq[0][hpq_idx(i, c)] = make_uint2(
                h2u(__floats2half2_rn(tmp_s[c0],     tmp_s[c0 + 1])),
                h2u(__floats2half2_rn(tmp_s[c0 + 8], tmp_s[c0 + 9])));
        }
    } else if (bid < BATCH + G3) {
        int g = bid - BATCH;   // 0..191
        int d = c;             // 0..63
        g_WihT[d * G3 + g] = W_ih[g * HDIM + d];
        g_WhhT[d * G3 + g] = W_hh[g * HDIM + d];
    } else if (c < 32) {
        // f16 B fragments for one (ctp, kt16)
        int q = bid - (BATCH + G3);   // 0..15
        int kt16 = q & 3, ctp = q >> 2;
        int tig = c & 3, gid = c >> 2;
        int k0 = kt16 * 16;
        int c0 = ctp * 16 + gid;      // ct0 column
        int c1 = c0 + 8;              // ct1 column
        uint32_t b00 = h2u(__floats2half2_rn(W_pool[(k0 + 2 * tig) * HDIM + c0],
                                             W_pool[(k0 + 2 * tig + 1) * HDIM + c0]));
        uint32_t b10 = h2u(__floats2half2_rn(W_pool[(k0 + 8 + 2 * tig) * HDIM + c0],
                                             W_pool[(k0 + 8 + 2 * tig + 1) * HDIM + c0]));
        uint32_t b01 = h2u(__floats2half2_rn(W_pool[(k0 + 2 * tig) * HDIM + c1],
                                             W_pool[(k0 + 2 * tig + 1) * HDIM + c1]));
        uint32_t b11 = h2u(__floats2half2_rn(W_pool[(k0 + 8 + 2 * tig) * HDIM + c1],
                                             W_pool[(k0 + 8 + 2 * tig + 1) * HDIM + c1]));
        g_B4[q * 32 + c] = make_uint4(b00, b10, b01, b11);
    }
}

// ---------------------------------------------------------------------------
// Persistent fused decoder (f16 MMA) — the 192.7us kernel with a leaner spool
// epilogue: D zero-init, hp folded post-MMA in f16 (1 pack-cvt per D-pair +
// HADD2), running max kept as half2 (HMAX2), hp loaded as uint2 (ct-pair per
// LDG.64). MMA count/order unchanged.
// Grid: 512 blocks x 128 threads, 4 blocks/SM co-resident (barrier safe).
// ---------------------------------------------------------------------------
__global__ void __launch_bounds__(128, 4) decode_kernel(
    const float* __restrict__ b_rel,
    const float* __restrict__ W_emb, const float* __restrict__ b_emb,
    const float* __restrict__ b_ih,  const float* __restrict__ b_hh,
    const float* __restrict__ W_pos, const float* __restrict__ b_pos,
    const float* __restrict__ W_rel, const float* __restrict__ W_pool,
    const float* __restrict__ b_pool, float* __restrict__ out)
{
    __shared__ __half2 ar_s[32];      // pair {b_rel - u_i} at kp
    __shared__ float red_s[4][HDIM];  // cross-warp max reduction
    __shared__ float pooled_s[HDIM];
    __shared__ float pos_s[2];
    __shared__ float emb_s[HDIM];
    __shared__ float hv_s[HDIM];
    __shared__ float hn_s[HDIM];
    __shared__ float hp_s[HDIM];
    __shared__ __align__(16) float gate_s[6][HDIM];
    __shared__ float4 hpr_s[16][4];

    int i = blockIdx.x;
    int t = threadIdx.x;
    int w = t >> 5, l = t & 31;
    int gid = l >> 2, tig = l & 3;

    #pragma unroll 1
    for (int step = 0; step < PRE; ++step) {
        const __half2* __restrict__ uhr = g_uh[step];
        const uint2*   __restrict__ hpq = g_hpq[step];

        if (t < 32) {
            float2 ui = __half22float2(uhr[pair_idx(i, t)]);
            ar_s[t] = __floats2half2_rn(b_rel[2 * t] - ui.x, b_rel[2 * t + 1] - ui.y);
        }
        __syncthreads();

        __half2 mx2[8];
        __half2 zero2 = __float2half2_rn(0.0f);
        #pragma unroll
        for (int ct = 0; ct < 8; ++ct) mx2[ct] = zero2;   // relu => max >= 0

        for (int p = 0; p < 4; ++p) {
            int jb = p * 128 + w * 32;
            int rb  = (jb >> 3) * 256;  // half2 row-block base (8 rows per 256)
            int r1  = rb + 512;         // second jtile (+16 rows)
            int rbq = (jb >> 3) * 128;  // uint2 hp base (8 rows per 128)
            int r1q = rbq + 256;

            // A fragments: e = hmax2(hadd2(u_j, ar), 0), packed f16, 2 jt x 4 kt16
            uint32_t afr[2][4][4];
            #pragma unroll
            for (int kt = 0; kt < 4; ++kt) {
                int kp0 = kt * 8 + tig;     // cols 2kp0, 2kp0+1
                int kp1 = kp0 + 4;          // cols +8
                __half2 ar0 = ar_s[kp0], ar1 = ar_s[kp1];
                #pragma unroll
                for (int jt = 0; jt < 2; ++jt) {
                    int r0 = rb + jt * 512;
                    __half2 v00 = uhr[r0 + kp0 * 8 + gid];          // row gid
                    __half2 v10 = uhr[r0 + 256 + kp0 * 8 + gid];    // row gid+8
                    __half2 v01 = uhr[r0 + kp1 * 8 + gid];
                    __half2 v11 = uhr[r0 + 256 + kp1 * 8 + gid];
                    afr[jt][kt][0] = h2u(__hmax2(__hadd2(v00, ar0), zero2));
                    afr[jt][kt][1] = h2u(__hmax2(__hadd2(v10, ar0), zero2));
                    afr[jt][kt][2] = h2u(__hmax2(__hadd2(v01, ar1), zero2));
                    afr[jt][kt][3] = h2u(__hmax2(__hadd2(v11, ar1), zero2));
                }
            }

            // ct pairs: 4 independent accumulator chains, 4 k16-steps each
            #pragma unroll
            for (int ctp = 0; ctp < 4; ++ctp) {
                int ct0 = 2 * ctp, ct1 = 2 * ctp + 1;
                // hp fragments: one LDG.64 per (jt, rowhalf); .x = ct0 pair, .y = ct1 pair
                int hb = (ctp * 4 + tig) * 8 + gid;
                uint2 q00 = hpq[rbq + hb];          // jt0 row gid
                uint2 q01 = hpq[rbq + 128 + hb];    // jt0 row gid+8
                uint2 q10 = hpq[r1q + hb];          // jt1 row gid
                uint2 q11 = hpq[r1q + 128 + hb];    // jt1 row gid+8

                float d00[4] = {0.f, 0.f, 0.f, 0.f};   // jt0, ct0
                float d01[4] = {0.f, 0.f, 0.f, 0.f};   // jt0, ct1
                float d10[4] = {0.f, 0.f, 0.f, 0.f};   // jt1, ct0
                float d11[4] = {0.f, 0.f, 0.f, 0.f};   // jt1, ct1

                #pragma unroll
                for (int kt = 0; kt < 4; ++kt) {
                    uint4 B = g_B4[(ctp * 4 + kt) * 32 + l];
                    mma_f16(d00, afr[0][kt][0], afr[0][kt][1], afr[0][kt][2], afr[0][kt][3], B.x, B.y);
                    mma_f16(d01, afr[0][kt][0], afr[0][kt][1], afr[0][kt][2], afr[0][kt][3], B.z, B.w);
                    mma_f16(d10, afr[1][kt][0], afr[1][kt][1], afr[1][kt][2], afr[1][kt][3], B.x, B.y);
                    mma_f16(d11, afr[1][kt][0], afr[1][kt][1], afr[1][kt][2], afr[1][kt][3], B.z, B.w);
                }
                // fold: pack D pair to f16x2, add hp (f16), max (f16)
                __half2 m0 = __hmax2(__hadd2(packh2(d00[1], d00[0]), u2h(q00.x)),
                                     __hadd2(packh2(d00[3], d00[2]), u2h(q01.x)));
                __half2 m0b = __hmax2(__hadd2(packh2(d10[1], d10[0]), u2h(q10.x)),
                                      __hadd2(packh2(d10[3], d10[2]), u2h(q11.x)));
                mx2[ct0] = __hmax2(mx2[ct0], __hmax2(m0, m0b));
                __half2 m1 = __hmax2(__hadd2(packh2(d01[1], d01[0]), u2h(q00.y)),
                                     __hadd2(packh2(d01[3], d01[2]), u2h(q01.y)));
                __half2 m1b = __hmax2(__hadd2(packh2(d11[1], d11[0]), u2h(q10.y)),
                                      __hadd2(packh2(d11[3], d11[2]), u2h(q11.y)));
                mx2[ct1] = __hmax2(mx2[ct1], __hmax2(m1, m1b));
            }
        }

        // Reduce across lane groups (gid) on half2, write per-warp result
        #pragma unroll
        for (int ct = 0; ct < 8; ++ct) {
            __half2 v = mx2[ct];
            v = __hmax2(v, u2h(__shfl_xor_sync(0xffffffffu, h2u(v), 4)));
            v = __hmax2(v, u2h(__shfl_xor_sync(0xffffffffu, h2u(v), 8)));
            v = __hmax2(v, u2h(__shfl_xor_sync(0xffffffffu, h2u(v), 16)));
            if (gid == 0) {
                float2 f = __half22float2(v);
                red_s[w][ct * 8 + 2 * tig]     = f.x;
                red_s[w][ct * 8 + 2 * tig + 1] = f.y;
            }
        }
        __syncthreads();
        if (t < HDIM)
            pooled_s[t] = fmaxf(fmaxf(red_s[0][t], red_s[1][t]), fmaxf(red_s[2][t], red_s[3][t]));
        __syncthreads();

        // ---- update tail ----
        if (w == 0) {
            float p0 = pooled_s[l], p1 = pooled_s[l + 32];
            float px = p0 * W_pos[l * 2 + 0] + p1 * W_pos[(l + 32) * 2 + 0];
            float py = p0 * W_pos[l * 2 + 1] + p1 * W_pos[(l + 32) * 2 + 1];
            #pragma unroll
            for (int s = 16; s; s >>= 1) {
                px += __shfl_xor_sync(0xffffffffu, px, s);
                py += __shfl_xor_sync(0xffffffffu, py, s);
            }
            if (l == 0) {
                px += b_pos[0]; py += b_pos[1];
                out[i * 2 * (OBS + PRE) + (OBS + step) * 2 + 0] = px;
                out[i * 2 * (OBS + PRE) + (OBS + step) * 2 + 1] = py;
                pos_s[0] = px; pos_s[1] = py;
            }
        }
        __syncthreads();

        float px = pos_s[0], py = pos_s[1];
        if (t < 32) {
            // next-step u pair (f16, fresh buffer: step+1)
            float u0 = px * W_rel[2 * t]     + py * W_rel[HDIM + 2 * t];
            float u1 = px * W_rel[2 * t + 1] + py * W_rel[HDIM + 2 * t + 1];
            g_uh[step + 1][pair_idx(i, t)] = __floats2half2_rn(u0, u1);
        }
        if (t < HDIM) {
            emb_s[t] = px * W_emb[t] + py * W_emb[HDIM + t] + b_emb[t];
            hv_s[t]  = g_h[i * HDIM + t];
        }
        __syncthreads();

        // Phase A: 6 GRU gate matvecs via float4 (thread = (gate g, c-quad q))
        if (t < 96) {
            int g = t >> 4, q = t & 15;
            int gg = (g < 3) ? g : g - 3;
            const float* Wt   = (g < 3) ? g_WihT : g_WhhT;
            const float* bias = (g < 3) ? b_ih : b_hh;
            const float* src  = (g < 3) ? emb_s : hv_s;
            float4 acc = *(const float4*)&bias[gg * 64 + q * 4];
            #pragma unroll 8
            for (int d = 0; d < HDIM; ++d) {
                float4 wv = *(const float4*)&Wt[d * G3 + gg * 64 + q * 4];
                float s = src[d];
                acc.x += s * wv.x; acc.y += s * wv.y;
                acc.z += s * wv.z; acc.w += s * wv.w;
            }
            *(float4*)&gate_s[g][q * 4] = acc;
        }
        __syncthreads();
        if (t < HDIM) {
            int c = t;
            float r = fsigmoid(gate_s[0][c] + gate_s[3][c]);
            float z = fsigmoid(gate_s[1][c] + gate_s[4][c]);
            float n = ftanh(gate_s[2][c] + r * gate_s[5][c]);
            float hn = (1.0f - z) * n + z * hv_s[c];
            g_h[i * HDIM + c] = hn;
            hn_s[c] = hn;
        }
        __syncthreads();

        // Phase B: hp = hn @ Wp2 + b_pool, float4 partials then reduce, f16 store
        if (t < 64) {
            int q = t & 15, dh = t >> 4;
            float4 acc = make_float4(0.0f, 0.0f, 0.0f, 0.0f);
            #pragma unroll
            for (int dd = 0; dd < 16; ++dd) {
                int d = dh * 16 + dd;
                float4 wv = *(const float4*)&W_pool[(HDIM + d) * HDIM + q * 4];
                float s = hn_s[d];
                acc.x += s * wv.x; acc.y += s * wv.y;
                acc.z += s * wv.z; acc.w += s * wv.w;
            }
            hpr_s[q][dh] = acc;
        }
        __syncthreads();
        if (t < 16) {
            int q = t;
            float4 a0 = hpr_s[q][0], a1 = hpr_s[q][1], a2 = hpr_s[q][2], a3 = hpr_s[q][3];
            hp_s[q * 4 + 0] = a0.x + a1.x + a2.x + a3.x + b_pool[q * 4 + 0];
            hp_s[q * 4 + 1] = a0.y + a1.y + a2.y + a3.y + b_pool[q * 4 + 1];
            hp_s[q * 4 + 2] = a0.z + a1.z + a2.z + a3.z + b_pool[q * 4 + 2];
            hp_s[q * 4 + 3] = a0.w + a1.w + a2.w + a3.w + b_pool[q * 4 + 3];
        }
        __syncthreads();
        if (t < 16) {
            int ctp = t >> 2, tg = t & 3;
            int c0 = 16 * ctp + 2 * tg;
            g_hpq[step + 1][hpq_idx(i, t)] = make_uint2(
                h2u(__floats2half2_rn(hp_s[c0],     hp_s[c0 + 1])),
                h2u(__floats2half2_rn(hp_s[c0 + 8], hp_s[c0 + 9])));
        }

        // ---- grid barrier (skip after last step) ----
        if (step == PRE - 1) break;
        __syncthreads();
        if (t == 0) {
            __threadfence();   // release: u/hp stores visible GPU-wide
            unsigned target = (unsigned)BATCH * (unsigned)(step + 1);
            unsigned old = atomicAdd(&g_bar_cnt, 1u);
            if (old + 1u == target) {
                atomicExch(&g_bar_rel, (unsigned)(step + 1));
            } else {
                unsigned v;
                do {
                    __nanosleep(128);
                    asm volatile("ld.global.cg.u32 %0, [%1];" : "=r"(v) : "l"(&g_bar_rel));
                } while (v < (unsigned)(step + 1));
            }
            __threadfence();
        }
        __syncthreads();
    }
}

// ---------------------------------------------------------------------------
extern "C" void kernel_launch(void* const* d_in, const int* in_sizes, int n_in,
                              void* d_out, int out_size)
{
    const float* hidden = (const float*)d_in[0];
    const float* gt     = (const float*)d_in[1];
    const float* W_emb  = (const float*)d_in[2];
    const float* b_emb  = (const float*)d_in[3];
    const float* W_ih   = (const float*)d_in[4];
    const float* W_hh   = (const float*)d_in[5];
    const float* b_ih   = (const float*)d_in[6];
    const float* b_hh   = (const float*)d_in[7];
    const float* W_pos  = (const float*)d_in[8];
    const float* b_pos  = (const float*)d_in[9];
    const float* W_rel  = (const float*)d_in[10];
    const float* b_rel  = (const float*)d_in[11];
    const float* W_pool = (const float*)d_in[12];
    const float* b_pool = (const float*)d_in[13];
    float* out = (float*)d_out;

    init_kernel<<<BATCH + G3 + 16, 64>>>(hidden, gt, W_ih, W_hh, W_rel, W_pool, b_pool, out);
    decode_kernel<<<BATCH, 128>>>(b_rel, W_emb, b_emb, b_ih, b_hh,
                                  W_pos, b_pos, W_rel, W_pool, b_pool, out);
}